// round 5
// baseline (speedup 1.0000x reference)
#include <cuda_runtime.h>
#include <cuda_fp16.h>

#define N_NODES 65536
#define N_EDGES 1048576
#define HID 80
#define EDGE_CHUNK 64
#define NPB 16   // nodes per transform block

// ---------------- static scratch (no allocations allowed) ----------------
__device__ __half2 g_hh[N_NODES * 40];        // h as fp16, 40 half2 per node (10 MB)
__device__ float2  g_A[N_NODES * 160];        // aggregate: 4 x 80 fp32 per node (84 MB)
__device__ int     g_deg[N_NODES];
__device__ int     g_rowptr[N_NODES + 1];
__device__ int     g_cursor[N_NODES];
__device__ int     g_csrc[N_EDGES];
__device__ float4  g_coef[N_EDGES];

// e3nn fan-in norms * 1/sqrt(2) * 1/sqrt(DEG=16)
#define K1C (0.03125f)
#define K2C (0.025515518f)
#define K3C (0.03125f)
#define K4C (0.044194174f)

// ---------------- preprocessing ----------------
__global__ void k_zero(int* __restrict__ deg) {
    int i = blockIdx.x * blockDim.x + threadIdx.x;
    if (i < N_NODES) deg[i] = 0;
}

__global__ void k_hist(const int* __restrict__ dst, int* __restrict__ deg) {
    int e = blockIdx.x * blockDim.x + threadIdx.x;
    if (e < N_EDGES) atomicAdd(&deg[dst[e]], 1);
}

// single-block (1024 threads) exclusive scan over 65536 ints; each thread owns 64
__global__ __launch_bounds__(1024) void k_scan(
    const int* __restrict__ deg, int* __restrict__ rowptr, int* __restrict__ cursor)
{
    __shared__ int wsum[32];
    int tid = threadIdx.x;
    int lane = tid & 31, wid = tid >> 5;
    int base = tid * 64;
    const int4* d4 = (const int4*)(deg + base);
    int s = 0;
#pragma unroll
    for (int i = 0; i < 16; i++) {
        int4 v = d4[i];
        s += v.x + v.y + v.z + v.w;
    }
    int v = s;
#pragma unroll
    for (int d = 1; d < 32; d <<= 1) {
        int t = __shfl_up_sync(0xffffffffu, v, d);
        if (lane >= d) v += t;
    }
    if (lane == 31) wsum[wid] = v;
    __syncthreads();
    if (wid == 0) {
        int w = wsum[lane];
        int wv = w;
#pragma unroll
        for (int d = 1; d < 32; d <<= 1) {
            int t = __shfl_up_sync(0xffffffffu, wv, d);
            if (lane >= d) wv += t;
        }
        wsum[lane] = wv - w;
    }
    __syncthreads();
    int off = wsum[wid] + (v - s);
#pragma unroll
    for (int i = 0; i < 16; i++) {
        int4 dv = d4[i];
        int b = base + i * 4;
        rowptr[b + 0] = off; cursor[b + 0] = off; off += dv.x;
        rowptr[b + 1] = off; cursor[b + 1] = off; off += dv.y;
        rowptr[b + 2] = off; cursor[b + 2] = off; off += dv.z;
        rowptr[b + 3] = off; cursor[b + 3] = off; off += dv.w;
    }
    if (tid == 1023) rowptr[N_NODES] = off;
}

__global__ void k_csr(const int* __restrict__ src, const int* __restrict__ dst,
                      const float4* __restrict__ eattr,
                      int* __restrict__ cursor, int* __restrict__ csrc,
                      float4* __restrict__ coef) {
    int e = blockIdx.x * blockDim.x + threadIdx.x;
    if (e >= N_EDGES) return;
    int d = dst[e];
    int pos = atomicAdd(&cursor[d], 1);
    csrc[pos] = src[e];
    coef[pos] = eattr[e];   // (s2, v2x, v2y, v2z)
}

// ---------------- input embed: h = x @ W_in + b_in, written as fp16 ----------------
__global__ void k_input(const float* __restrict__ x, const float* __restrict__ W_in,
                        const float* __restrict__ b_in, __half2* __restrict__ hh) {
    int id = blockIdx.x * blockDim.x + threadIdx.x;   // N*40
    if (id >= N_NODES * 40) return;
    int n = id / 40, p = id % 40;
    int c0 = 2 * p, c1 = c0 + 1;
    const float* xr = x + n * 16;
    float a0 = b_in[c0], a1 = b_in[c1];
#pragma unroll
    for (int i = 0; i < 16; i++) {
        float xi = xr[i];
        a0 = fmaf(xi, W_in[i * HID + c0], a0);
        a1 = fmaf(xi, W_in[i * HID + c1], a1);
    }
    hh[id] = __floats2half2_rn(a0, a1);
}

// ---------------- aggregation: A[n] = sum_e coef_e (x) h[src_e] --------------------
// one 64-thread block per dst node; threads 0..39 each own 2 h-channels (one half2)
__global__ __launch_bounds__(64) void k_agg(
    const __half2* __restrict__ hh, const int* __restrict__ rowptr,
    const int* __restrict__ csrc, const float4* __restrict__ coef,
    float2* __restrict__ A)
{
    __shared__ int    s_src[EDGE_CHUNK];
    __shared__ float4 s_cf[EDGE_CHUNK];
    int n = blockIdx.x;
    int tid = threadIdx.x;
    int beg = rowptr[n], end = rowptr[n + 1];
    float2 a0 = {0.f, 0.f}, a1 = {0.f, 0.f}, a2 = {0.f, 0.f}, a3 = {0.f, 0.f};
    for (int base = beg; base < end; base += EDGE_CHUNK) {
        int cnt = min(EDGE_CHUNK, end - base);
        __syncthreads();
        if (tid < cnt) {
            s_src[tid] = csrc[base + tid];
            s_cf[tid]  = coef[base + tid];
        }
        __syncthreads();
        if (tid < 40) {
#pragma unroll 4
            for (int i = 0; i < cnt; i++) {
                int s = s_src[i];
                float4 cf = s_cf[i];
                float2 f = __half22float2(hh[s * 40 + tid]);
                a0.x = fmaf(cf.x, f.x, a0.x); a0.y = fmaf(cf.x, f.y, a0.y);
                a1.x = fmaf(cf.y, f.x, a1.x); a1.y = fmaf(cf.y, f.y, a1.y);
                a2.x = fmaf(cf.z, f.x, a2.x); a2.y = fmaf(cf.z, f.y, a2.y);
                a3.x = fmaf(cf.w, f.x, a3.x); a3.y = fmaf(cf.w, f.y, a3.y);
            }
        }
    }
    if (tid < 40) {
        float2* An = A + n * 160;     // layout [4][80] as float2 [4][40]
        An[0 * 40 + tid] = a0;        // A_s
        An[1 * 40 + tid] = a1;        // A_x
        An[2 * 40 + tid] = a2;        // A_y
        An[3 * 40 + tid] = a3;        // A_z
    }
}

// ---------------- per-node transform of aggregate A -> h_next (fp16) --------------
// 192 threads, 16 nodes/block, thread = (node-pair g, channel-pair cp)
__device__ __forceinline__ void trans_core(
    const float* s_A, const float* s_w1, const float* s_w2,
    const float* s_w3, const float* s_w4,
    int g, int cp, float* oA, float* oB)   // oA/oB: up to 6 outputs per node
{
    const float* AA = s_A + (2 * g) * 320;
    const float* AB = AA + 320;
    if (cp < 16) {
        int c0 = 2 * cp, c1 = c0 + 1;
        float pA0 = 0.f, pA1 = 0.f, pB0 = 0.f, pB1 = 0.f;
#pragma unroll
        for (int a = 0; a < 32; a++) {
            float u = s_w1[a * 32 + c0], v = s_w1[a * 32 + c1];
            float xA = AA[a], xB = AB[a];
            pA0 = fmaf(xA, u, pA0); pA1 = fmaf(xA, v, pA1);
            pB0 = fmaf(xB, u, pB0); pB1 = fmaf(xB, v, pB1);
        }
#pragma unroll
        for (int a = 0; a < 16; a++) {
            float u = s_w2[a * 32 + c0], v = s_w2[a * 32 + c1];
#pragma unroll
            for (int k = 0; k < 3; k++) {
                float tA = AA[(1 + k) * 80 + 32 + 3 * a + k];
                float tB = AB[(1 + k) * 80 + 32 + 3 * a + k];
                pA0 = fmaf(tA, u, pA0); pA1 = fmaf(tA, v, pA1);
                pB0 = fmaf(tB, u, pB0); pB1 = fmaf(tB, v, pB1);
            }
        }
        oA[0] = pA0; oA[1] = pA1; oB[0] = pB0; oB[1] = pB1;
    } else {
        int c0 = 2 * (cp - 16), c1 = c0 + 1;
        float rA[6] = {0,0,0,0,0,0}, rB[6] = {0,0,0,0,0,0};  // [c][k]
#pragma unroll
        for (int a = 0; a < 32; a++) {
            float u = s_w3[a * 16 + c0], v = s_w3[a * 16 + c1];
#pragma unroll
            for (int k = 0; k < 3; k++) {
                float tA = AA[(1 + k) * 80 + a];
                float tB = AB[(1 + k) * 80 + a];
                rA[k]     = fmaf(tA, u, rA[k]);     rA[3 + k] = fmaf(tA, v, rA[3 + k]);
                rB[k]     = fmaf(tB, u, rB[k]);     rB[3 + k] = fmaf(tB, v, rB[3 + k]);
            }
        }
#pragma unroll
        for (int a = 0; a < 16; a++) {
            float u = s_w4[a * 16 + c0], v = s_w4[a * 16 + c1];
#pragma unroll
            for (int k = 0; k < 3; k++) {
                float tA = AA[32 + 3 * a + k];
                float tB = AB[32 + 3 * a + k];
                rA[k]     = fmaf(tA, u, rA[k]);     rA[3 + k] = fmaf(tA, v, rA[3 + k]);
                rB[k]     = fmaf(tB, u, rB[k]);     rB[3 + k] = fmaf(tB, v, rB[3 + k]);
            }
        }
#pragma unroll
        for (int i = 0; i < 6; i++) { oA[i] = rA[i]; oB[i] = rB[i]; }
    }
}

// weights staged PRESCALED: s_w1 *= K1, s_w2 *= K2, s_w3 *= K3, s_w4' mixes both:
// (w4 path shares accumulator with w3 path, so prescale w4 by K4 and w3 by K3)
__device__ __forceinline__ void stage_weights(
    int tid, int nthreads,
    const float* w1, const float* w2, const float* w3, const float* w4,
    float* s_w1, float* s_w2, float* s_w3, float* s_w4)
{
    for (int i = tid; i < 1024; i += nthreads) s_w1[i] = K1C * w1[i];
    for (int i = tid; i < 512;  i += nthreads) s_w2[i] = K2C * w2[i];
    for (int i = tid; i < 512;  i += nthreads) s_w3[i] = K3C * w3[i];
    for (int i = tid; i < 256;  i += nthreads) s_w4[i] = K4C * w4[i];
}

__global__ __launch_bounds__(192) void k_trans(
    const float* __restrict__ A,
    const float* __restrict__ w1, const float* __restrict__ w2,
    const float* __restrict__ w3, const float* __restrict__ w4,
    __half2* __restrict__ hh)
{
    __shared__ float s_w1[1024], s_w2[512], s_w3[512], s_w4[256];
    __shared__ float s_A[NPB * 320];
    int tid = threadIdx.x;
    stage_weights(tid, 192, w1, w2, w3, w4, s_w1, s_w2, s_w3, s_w4);
    int nb = blockIdx.x * NPB;
    {
        const float4* A4 = (const float4*)(A + nb * 320);
        float4* sA4 = (float4*)s_A;
        for (int i = tid; i < NPB * 80; i += 192) sA4[i] = A4[i];
    }
    __syncthreads();
    int g = tid / 24, cp = tid % 24;
    float oA[6], oB[6];
    trans_core(s_A, s_w1, s_w2, s_w3, s_w4, g, cp, oA, oB);
    __half2* hA = hh + (nb + 2 * g) * 40;
    __half2* hB = hA + 40;
    if (cp < 16) {
        hA[cp] = __floats2half2_rn(oA[0], oA[1]);
        hB[cp] = __floats2half2_rn(oB[0], oB[1]);
    } else {
        int m = cp - 16;   // outputs at half positions 32+6m .. 37+6m
        hA[16 + 3 * m + 0] = __floats2half2_rn(oA[0], oA[1]);
        hA[16 + 3 * m + 1] = __floats2half2_rn(oA[2], oA[3]);
        hA[16 + 3 * m + 2] = __floats2half2_rn(oA[4], oA[5]);
        hB[16 + 3 * m + 0] = __floats2half2_rn(oB[0], oB[1]);
        hB[16 + 3 * m + 1] = __floats2half2_rn(oB[2], oB[3]);
        hB[16 + 3 * m + 2] = __floats2half2_rn(oB[4], oB[5]);
    }
}

// final layer transform fused with ReLU + W_out readout
__global__ __launch_bounds__(192) void k_trans_final(
    const float* __restrict__ A,
    const float* __restrict__ w1, const float* __restrict__ w2,
    const float* __restrict__ w3, const float* __restrict__ w4,
    const float* __restrict__ W_out, const float* __restrict__ b_out,
    float* __restrict__ out)
{
    __shared__ float s_w1[1024], s_w2[512], s_w3[512], s_w4[256];
    __shared__ float s_A[NPB * 320];
    __shared__ float s_o[NPB][HID];
    __shared__ float s_Wo[HID * 8];
    int tid = threadIdx.x;
    stage_weights(tid, 192, w1, w2, w3, w4, s_w1, s_w2, s_w3, s_w4);
    for (int i = tid; i < HID * 8; i += 192) s_Wo[i] = W_out[i];
    int nb = blockIdx.x * NPB;
    {
        const float4* A4 = (const float4*)(A + nb * 320);
        float4* sA4 = (float4*)s_A;
        for (int i = tid; i < NPB * 80; i += 192) sA4[i] = A4[i];
    }
    __syncthreads();
    int g = tid / 24, cp = tid % 24;
    float oA[6], oB[6];
    trans_core(s_A, s_w1, s_w2, s_w3, s_w4, g, cp, oA, oB);
    int nA = 2 * g, nB = nA + 1;
    if (cp < 16) {
        int c0 = 2 * cp;
        s_o[nA][c0]     = fmaxf(oA[0], 0.f);
        s_o[nA][c0 + 1] = fmaxf(oA[1], 0.f);
        s_o[nB][c0]     = fmaxf(oB[0], 0.f);
        s_o[nB][c0 + 1] = fmaxf(oB[1], 0.f);
    } else {
        int c0 = 2 * (cp - 16);
#pragma unroll
        for (int k = 0; k < 3; k++) {
            s_o[nA][32 + 3 * c0 + k]     = fmaxf(oA[k], 0.f);
            s_o[nA][32 + 3 * (c0+1) + k] = fmaxf(oA[3 + k], 0.f);
            s_o[nB][32 + 3 * c0 + k]     = fmaxf(oB[k], 0.f);
            s_o[nB][32 + 3 * (c0+1) + k] = fmaxf(oB[3 + k], 0.f);
        }
    }
    __syncthreads();
    if (tid < NPB * 8) {
        int node = tid / 8, o = tid % 8;
        float acc = b_out[o];
        const float* so = s_o[node];
#pragma unroll
        for (int c = 0; c < HID; c++)
            acc = fmaf(so[c], s_Wo[c * 8 + o], acc);
        out[(nb + node) * 8 + o] = acc;
    }
}

// ---------------- launch ----------------
extern "C" void kernel_launch(void* const* d_in, const int* in_sizes, int n_in,
                              void* d_out, int out_size) {
    const float* x     = (const float*)d_in[0];
    const int*   eidx  = (const int*)d_in[1];     // (2, E) int32: row0=src, row1=dst
    const float* eattr = (const float*)d_in[2];   // (E, 4)
    const float* W_in  = (const float*)d_in[3];
    const float* b_in  = (const float*)d_in[4];
    const float* tpw1  = (const float*)d_in[5];   // (3,32,32)
    const float* tpw2  = (const float*)d_in[6];   // (3,16,32)
    const float* tpw3  = (const float*)d_in[7];   // (3,32,16)
    const float* tpw4  = (const float*)d_in[8];   // (3,16,16)
    const float* W_out = (const float*)d_in[9];
    const float* b_out = (const float*)d_in[10];
    float* out = (float*)d_out;

    __half2 *hh; float2 *A; float4 *coef; int *deg, *rowptr, *cursor, *csrc;
    cudaGetSymbolAddress((void**)&hh,     g_hh);
    cudaGetSymbolAddress((void**)&A,      g_A);
    cudaGetSymbolAddress((void**)&deg,    g_deg);
    cudaGetSymbolAddress((void**)&rowptr, g_rowptr);
    cudaGetSymbolAddress((void**)&cursor, g_cursor);
    cudaGetSymbolAddress((void**)&csrc,   g_csrc);
    cudaGetSymbolAddress((void**)&coef,   g_coef);

    const int* src = eidx;
    const int* dst = eidx + N_EDGES;

    // CSR build
    k_zero<<<N_NODES / 256, 256>>>(deg);
    k_hist<<<N_EDGES / 256, 256>>>(dst, deg);
    k_scan<<<1, 1024>>>(deg, rowptr, cursor);
    k_csr<<<N_EDGES / 256, 256>>>(src, dst, (const float4*)eattr, cursor, csrc, coef);

    // input embed (fp16 h)
    k_input<<<(N_NODES * 40) / 256, 256>>>(x, W_in, b_in, hh);

    // layers 0,1: aggregate then transform
    for (int l = 0; l < 2; l++) {
        k_agg<<<N_NODES, 64>>>(hh, rowptr, csrc, coef, A);
        k_trans<<<N_NODES / NPB, 192>>>((const float*)A,
            tpw1 + l * 32 * 32, tpw2 + l * 16 * 32,
            tpw3 + l * 32 * 16, tpw4 + l * 16 * 16, hh);
    }

    // layer 2: aggregate then fused transform + readout
    k_agg<<<N_NODES, 64>>>(hh, rowptr, csrc, coef, A);
    k_trans_final<<<N_NODES / NPB, 192>>>((const float*)A,
        tpw1 + 2 * 32 * 32, tpw2 + 2 * 16 * 32,
        tpw3 + 2 * 32 * 16, tpw4 + 2 * 16 * 16, W_out, b_out, out);
}

// round 6
// speedup vs baseline: 1.7642x; 1.7642x over previous
#include <cuda_runtime.h>
#include <cuda_fp16.h>

#define N_NODES 65536
#define N_EDGES 1048576
#define HID 80
#define NCH 48   // 32 scalar channels + 16 vector channels
#define EDGE_CHUNK 64
#define NPB 16   // nodes per k_node block

// ---------------- static scratch (no allocations allowed) ----------------
__device__ __half2 g_hh[N_NODES * 40];       // h as fp16: 40 half2/node (10.5 MB)
__device__ uint2   g_V[N_NODES * NCH];       // 4 x fp16 per channel (25 MB)
__device__ int     g_deg[N_NODES];
__device__ int     g_rowptr[N_NODES + 1];
__device__ int     g_cursor[N_NODES];
__device__ int     g_csrc[N_EDGES];
__device__ uint2   g_coefh[N_EDGES];         // 4 x fp16 coef (8 MB)

// e3nn fan-in norms * 1/sqrt(2) * 1/sqrt(DEG=16)
#define K1C (0.03125f)
#define K2C (0.025515518f)
#define K3C (0.03125f)
#define K4C (0.044194174f)

__device__ __forceinline__ uint2 pack4h(float a, float b, float c, float d) {
    __half2 lo = __floats2half2_rn(a, b);
    __half2 hi = __floats2half2_rn(c, d);
    uint2 r;
    r.x = *(const unsigned int*)&lo;
    r.y = *(const unsigned int*)&hi;
    return r;
}

__device__ __forceinline__ float4 unpack4h(uint2 p) {
    float2 lo = __half22float2(*(const __half2*)&p.x);
    float2 hi = __half22float2(*(const __half2*)&p.y);
    return make_float4(lo.x, lo.y, hi.x, hi.y);
}

// ---------------- preprocessing ----------------
__global__ void k_zero(int* __restrict__ deg) {
    int i = blockIdx.x * blockDim.x + threadIdx.x;
    if (i < N_NODES) deg[i] = 0;
}

__global__ void k_hist(const int* __restrict__ dst, int* __restrict__ deg) {
    int e = blockIdx.x * blockDim.x + threadIdx.x;
    if (e < N_EDGES) atomicAdd(&deg[dst[e]], 1);
}

// single-block (1024 threads) exclusive scan over 65536 ints; each thread owns 64
__global__ __launch_bounds__(1024) void k_scan(
    const int* __restrict__ deg, int* __restrict__ rowptr, int* __restrict__ cursor)
{
    __shared__ int wsum[32];
    int tid = threadIdx.x;
    int lane = tid & 31, wid = tid >> 5;
    int base = tid * 64;
    const int4* d4 = (const int4*)(deg + base);
    int s = 0;
#pragma unroll
    for (int i = 0; i < 16; i++) {
        int4 v = d4[i];
        s += v.x + v.y + v.z + v.w;
    }
    int v = s;
#pragma unroll
    for (int d = 1; d < 32; d <<= 1) {
        int t = __shfl_up_sync(0xffffffffu, v, d);
        if (lane >= d) v += t;
    }
    if (lane == 31) wsum[wid] = v;
    __syncthreads();
    if (wid == 0) {
        int w = wsum[lane];
        int wv = w;
#pragma unroll
        for (int d = 1; d < 32; d <<= 1) {
            int t = __shfl_up_sync(0xffffffffu, wv, d);
            if (lane >= d) wv += t;
        }
        wsum[lane] = wv - w;
    }
    __syncthreads();
    int off = wsum[wid] + (v - s);
#pragma unroll
    for (int i = 0; i < 16; i++) {
        int4 dv = d4[i];
        int b = base + i * 4;
        rowptr[b + 0] = off; cursor[b + 0] = off; off += dv.x;
        rowptr[b + 1] = off; cursor[b + 1] = off; off += dv.y;
        rowptr[b + 2] = off; cursor[b + 2] = off; off += dv.z;
        rowptr[b + 3] = off; cursor[b + 3] = off; off += dv.w;
    }
    if (tid == 1023) rowptr[N_NODES] = off;
}

__global__ void k_csr(const int* __restrict__ src, const int* __restrict__ dst,
                      const float4* __restrict__ eattr,
                      int* __restrict__ cursor, int* __restrict__ csrc,
                      uint2* __restrict__ coefh) {
    int e = blockIdx.x * blockDim.x + threadIdx.x;
    if (e >= N_EDGES) return;
    int d = dst[e];
    int pos = atomicAdd(&cursor[d], 1);
    csrc[pos] = src[e];
    float4 cf = eattr[e];
    coefh[pos] = pack4h(cf.x, cf.y, cf.z, cf.w);   // (s2, v2x, v2y, v2z)
}

// ---------------- input embed: h = x @ W_in + b_in (fp16 out) ----------------
__global__ void k_input(const float* __restrict__ x, const float* __restrict__ W_in,
                        const float* __restrict__ b_in, __half2* __restrict__ hh) {
    int id = blockIdx.x * blockDim.x + threadIdx.x;   // N*40
    if (id >= N_NODES * 40) return;
    int n = id / 40, p = id % 40;
    int c0 = 2 * p, c1 = c0 + 1;
    const float* xr = x + n * 16;
    float a0 = b_in[c0], a1 = b_in[c1];
#pragma unroll
    for (int i = 0; i < 16; i++) {
        float xi = xr[i];
        a0 = fmaf(xi, W_in[i * HID + c0], a0);
        a1 = fmaf(xi, W_in[i * HID + c1], a1);
    }
    hh[id] = __floats2half2_rn(a0, a1);
}

// ---------------- per-node transform: register-blocked 2 nodes x 2 channels ----
__global__ __launch_bounds__(192) void k_node(
    const __half2* __restrict__ hh,
    const float* __restrict__ w1, const float* __restrict__ w2,
    const float* __restrict__ w3, const float* __restrict__ w4,
    uint2* __restrict__ V)
{
    __shared__ float s_w1[1024];   // 32x32, prescaled K1
    __shared__ float s_w2[512];    // 16x32, prescaled K2
    __shared__ float s_w3[512];    // 32x16, prescaled K3
    __shared__ float s_w4[256];    // 16x16, prescaled K4
    __shared__ float s_h[NPB][HID];
    int tid = threadIdx.x;
    for (int i = tid; i < 1024; i += 192) s_w1[i] = K1C * w1[i];
    for (int i = tid; i < 512;  i += 192) s_w2[i] = K2C * w2[i];
    for (int i = tid; i < 512;  i += 192) s_w3[i] = K3C * w3[i];
    for (int i = tid; i < 256;  i += 192) s_w4[i] = K4C * w4[i];
    int nb = blockIdx.x * NPB;
    {
        // 16 nodes x 40 half2 = 640 half2 = 320 uint2 loads, each -> 4 floats
        const uint2* h4 = (const uint2*)(hh + nb * 40);
        float4* sh4 = (float4*)&s_h[0][0];
        for (int i = tid; i < NPB * 20; i += 192) sh4[i] = unpack4h(h4[i]);
    }
    __syncthreads();

    int g  = tid / 24;   // node pair 0..7
    int cp = tid % 24;   // channel pair
    const float* hA = s_h[2 * g];
    const float* hB = s_h[2 * g + 1];
    uint2* VA = V + (nb + 2 * g) * NCH;
    uint2* VB = V + (nb + 2 * g + 1) * NCH;

    if (cp < 16) {
        int c0 = 2 * cp, c1 = c0 + 1;
        float pA0 = 0.f, pA1 = 0.f, pB0 = 0.f, pB1 = 0.f;
#pragma unroll
        for (int a = 0; a < 32; a++) {
            float xA = hA[a], xB = hB[a];
            float u = s_w1[a * 32 + c0], v = s_w1[a * 32 + c1];
            pA0 = fmaf(xA, u, pA0); pA1 = fmaf(xA, v, pA1);
            pB0 = fmaf(xB, u, pB0); pB1 = fmaf(xB, v, pB1);
        }
        float tA0x = 0.f, tA0y = 0.f, tA0z = 0.f;
        float tA1x = 0.f, tA1y = 0.f, tA1z = 0.f;
        float tB0x = 0.f, tB0y = 0.f, tB0z = 0.f;
        float tB1x = 0.f, tB1y = 0.f, tB1z = 0.f;
#pragma unroll
        for (int a = 0; a < 16; a++) {
            float u = s_w2[a * 32 + c0], v = s_w2[a * 32 + c1];
            float xA = hA[32 + a * 3], yA = hA[32 + a * 3 + 1], zA = hA[32 + a * 3 + 2];
            float xB = hB[32 + a * 3], yB = hB[32 + a * 3 + 1], zB = hB[32 + a * 3 + 2];
            tA0x = fmaf(xA, u, tA0x); tA0y = fmaf(yA, u, tA0y); tA0z = fmaf(zA, u, tA0z);
            tA1x = fmaf(xA, v, tA1x); tA1y = fmaf(yA, v, tA1y); tA1z = fmaf(zA, v, tA1z);
            tB0x = fmaf(xB, u, tB0x); tB0y = fmaf(yB, u, tB0y); tB0z = fmaf(zB, u, tB0z);
            tB1x = fmaf(xB, v, tB1x); tB1y = fmaf(yB, v, tB1y); tB1z = fmaf(zB, v, tB1z);
        }
        VA[c0] = pack4h(pA0, tA0x, tA0y, tA0z);
        VA[c1] = pack4h(pA1, tA1x, tA1y, tA1z);
        VB[c0] = pack4h(pB0, tB0x, tB0y, tB0z);
        VB[c1] = pack4h(pB1, tB1x, tB1y, tB1z);
    } else {
        int c0 = (cp - 16) * 2, c1 = c0 + 1;
        float pA0 = 0.f, pA1 = 0.f, pB0 = 0.f, pB1 = 0.f;
#pragma unroll
        for (int a = 0; a < 32; a++) {
            float xA = hA[a], xB = hB[a];
            float u = s_w3[a * 16 + c0], v = s_w3[a * 16 + c1];
            pA0 = fmaf(xA, u, pA0); pA1 = fmaf(xA, v, pA1);
            pB0 = fmaf(xB, u, pB0); pB1 = fmaf(xB, v, pB1);
        }
        float tA0x = 0.f, tA0y = 0.f, tA0z = 0.f;
        float tA1x = 0.f, tA1y = 0.f, tA1z = 0.f;
        float tB0x = 0.f, tB0y = 0.f, tB0z = 0.f;
        float tB1x = 0.f, tB1y = 0.f, tB1z = 0.f;
#pragma unroll
        for (int a = 0; a < 16; a++) {
            float u = s_w4[a * 16 + c0], v = s_w4[a * 16 + c1];
            float xA = hA[32 + a * 3], yA = hA[32 + a * 3 + 1], zA = hA[32 + a * 3 + 2];
            float xB = hB[32 + a * 3], yB = hB[32 + a * 3 + 1], zB = hB[32 + a * 3 + 2];
            tA0x = fmaf(xA, u, tA0x); tA0y = fmaf(yA, u, tA0y); tA0z = fmaf(zA, u, tA0z);
            tA1x = fmaf(xA, v, tA1x); tA1y = fmaf(yA, v, tA1y); tA1z = fmaf(zA, v, tA1z);
            tB0x = fmaf(xB, u, tB0x); tB0y = fmaf(yB, u, tB0y); tB0z = fmaf(zB, u, tB0z);
            tB1x = fmaf(xB, v, tB1x); tB1y = fmaf(yB, v, tB1y); tB1z = fmaf(zB, v, tB1z);
        }
        VA[32 + c0] = pack4h(pA0, tA0x, tA0y, tA0z);
        VA[32 + c1] = pack4h(pA1, tA1x, tA1y, tA1z);
        VB[32 + c0] = pack4h(pB0, tB0x, tB0y, tB0z);
        VB[32 + c1] = pack4h(pB1, tB1x, tB1y, tB1z);
    }
}

// ---------------- aggregation: one block (64 threads) per dst node ----------------
__device__ __forceinline__ void agg_node(
    const uint2* __restrict__ V, const int* __restrict__ rowptr,
    const int* __restrict__ csrc, const uint2* __restrict__ coefh,
    int n, int tid, int* s_src, float4* s_cf,
    float& a0, float& a1, float& a2)
{
    int beg = rowptr[n], end = rowptr[n + 1];
    int ch = tid;
    bool is_s = (ch < 32);
    a0 = a1 = a2 = 0.f;
    for (int base = beg; base < end; base += EDGE_CHUNK) {
        int cnt = min(EDGE_CHUNK, end - base);
        __syncthreads();
        if (tid < cnt) {
            s_src[tid] = csrc[base + tid];
            s_cf[tid]  = unpack4h(coefh[base + tid]);   // convert once, here
        }
        __syncthreads();
        if (ch < NCH) {
#pragma unroll 8
            for (int i = 0; i < cnt; i++) {
                int s = s_src[i];
                float4 cf = s_cf[i];
                uint2 vp = V[s * NCH + ch];
                float2 f0 = __half22float2(*(const __half2*)&vp.x);  // (P, t.x)
                float2 f1 = __half22float2(*(const __half2*)&vp.y);  // (t.y, t.z)
                if (is_s) {
                    a0 = fmaf(cf.x, f0.x, a0);
                    a0 = fmaf(cf.y, f0.y, a0);
                    a0 = fmaf(cf.z, f1.x, a0);
                    a0 = fmaf(cf.w, f1.y, a0);
                } else {
                    a0 = fmaf(cf.y, f0.x, fmaf(cf.x, f0.y, a0));
                    a1 = fmaf(cf.z, f0.x, fmaf(cf.x, f1.x, a1));
                    a2 = fmaf(cf.w, f0.x, fmaf(cf.x, f1.y, a2));
                }
            }
        }
    }
}

__global__ __launch_bounds__(64) void k_agg(
    const uint2* __restrict__ V, const int* __restrict__ rowptr,
    const int* __restrict__ csrc, const uint2* __restrict__ coefh,
    __half2* __restrict__ hh)
{
    __shared__ int    s_src[EDGE_CHUNK];
    __shared__ float4 s_cf[EDGE_CHUNK];
    __shared__ float  s_out[HID];
    int n = blockIdx.x;
    int tid = threadIdx.x;
    float a0, a1, a2;
    agg_node(V, rowptr, csrc, coefh, n, tid, s_src, s_cf, a0, a1, a2);
    __syncthreads();
    if (tid < 32) {
        s_out[tid] = a0;
    } else if (tid < NCH) {
        int b = 32 + (tid - 32) * 3;
        s_out[b + 0] = a0;
        s_out[b + 1] = a1;
        s_out[b + 2] = a2;
    }
    __syncthreads();
    if (tid < 40)
        hh[n * 40 + tid] = __floats2half2_rn(s_out[2 * tid], s_out[2 * tid + 1]);
}

// last layer: fuse ReLU + W_out readout
__global__ __launch_bounds__(64) void k_agg_final(
    const uint2* __restrict__ V, const int* __restrict__ rowptr,
    const int* __restrict__ csrc, const uint2* __restrict__ coefh,
    const float* __restrict__ W_out, const float* __restrict__ b_out,
    float* __restrict__ out)
{
    __shared__ int    s_src[EDGE_CHUNK];
    __shared__ float4 s_cf[EDGE_CHUNK];
    __shared__ float  sh[HID];
    int n = blockIdx.x;
    int tid = threadIdx.x;
    float a0, a1, a2;
    agg_node(V, rowptr, csrc, coefh, n, tid, s_src, s_cf, a0, a1, a2);
    __syncthreads();
    if (tid < 32) {
        sh[tid] = fmaxf(a0, 0.f);
    } else if (tid < NCH) {
        int b = 32 + (tid - 32) * 3;
        sh[b + 0] = fmaxf(a0, 0.f);
        sh[b + 1] = fmaxf(a1, 0.f);
        sh[b + 2] = fmaxf(a2, 0.f);
    }
    __syncthreads();
    if (tid < 8) {
        float acc = b_out[tid];
#pragma unroll
        for (int c = 0; c < HID; c++)
            acc = fmaf(sh[c], W_out[c * 8 + tid], acc);
        out[n * 8 + tid] = acc;
    }
}

// ---------------- launch ----------------
extern "C" void kernel_launch(void* const* d_in, const int* in_sizes, int n_in,
                              void* d_out, int out_size) {
    const float* x     = (const float*)d_in[0];
    const int*   eidx  = (const int*)d_in[1];     // (2, E) int32: row0=src, row1=dst
    const float* eattr = (const float*)d_in[2];   // (E, 4)
    const float* W_in  = (const float*)d_in[3];
    const float* b_in  = (const float*)d_in[4];
    const float* tpw1  = (const float*)d_in[5];   // (3,32,32)
    const float* tpw2  = (const float*)d_in[6];   // (3,16,32)
    const float* tpw3  = (const float*)d_in[7];   // (3,32,16)
    const float* tpw4  = (const float*)d_in[8];   // (3,16,16)
    const float* W_out = (const float*)d_in[9];
    const float* b_out = (const float*)d_in[10];
    float* out = (float*)d_out;

    __half2 *hh; uint2 *V, *coefh; int *deg, *rowptr, *cursor, *csrc;
    cudaGetSymbolAddress((void**)&hh,     g_hh);
    cudaGetSymbolAddress((void**)&V,      g_V);
    cudaGetSymbolAddress((void**)&deg,    g_deg);
    cudaGetSymbolAddress((void**)&rowptr, g_rowptr);
    cudaGetSymbolAddress((void**)&cursor, g_cursor);
    cudaGetSymbolAddress((void**)&csrc,   g_csrc);
    cudaGetSymbolAddress((void**)&coefh,  g_coefh);

    const int* src = eidx;
    const int* dst = eidx + N_EDGES;

    // CSR build
    k_zero<<<N_NODES / 256, 256>>>(deg);
    k_hist<<<N_EDGES / 256, 256>>>(dst, deg);
    k_scan<<<1, 1024>>>(deg, rowptr, cursor);
    k_csr<<<N_EDGES / 256, 256>>>(src, dst, (const float4*)eattr, cursor, csrc, coefh);

    // input embed (fp16 h)
    k_input<<<(N_NODES * 40) / 256, 256>>>(x, W_in, b_in, hh);

    // layers 0,1: node transform + aggregate (h updated in place; k_agg never reads h)
    for (int l = 0; l < 2; l++) {
        k_node<<<N_NODES / NPB, 192>>>(hh,
            tpw1 + l * 32 * 32, tpw2 + l * 16 * 32,
            tpw3 + l * 32 * 16, tpw4 + l * 16 * 16, V);
        k_agg<<<N_NODES, 64>>>(V, rowptr, csrc, coefh, hh);
    }

    // layer 2 fused with readout
    k_node<<<N_NODES / NPB, 192>>>(hh,
        tpw1 + 2 * 32 * 32, tpw2 + 2 * 16 * 32,
        tpw3 + 2 * 32 * 16, tpw4 + 2 * 16 * 16, V);
    k_agg_final<<<N_NODES, 64>>>(V, rowptr, csrc, coefh, W_out, b_out, out);
}